// round 1
// baseline (speedup 1.0000x reference)
#include <cuda_runtime.h>

// Problem constants (fixed shapes from reference)
#define B_   2
#define T_   32
#define C_   128
#define G_   4
#define CPG  32      // channels per group = C/G
#define H_   64
#define W_   64
#define HC_  16      // coarse h
#define WC_  16      // coarse w
#define TQ   8       // q-chunk per block
#define HW_  (H_*W_)     // 4096
#define CHW_ (C_*HW_)    // 524288

// out[b,q,g*CPG+c,h,w] = sum_k A_fine[g,b,q,k,h,w] * x[b,k,g*CPG+c,h,w]
// A_fine = bilinear upsample (x4, half-pixel centers, edge clamp) of attn.

__global__ __launch_bounds__(256) void temporal_agg_kernel(
    const float* __restrict__ x,
    const float* __restrict__ attn,
    float* __restrict__ out)
{
    __shared__ float Cy[TQ * T_ * WC_];   // y-lerped coarse attn  [q][k][wc]  16 KB
    __shared__ float Ash[TQ * T_ * 32];   // fine attn for this w-chunk [q][k][w] 32 KB

    const int qc  = blockIdx.x;          // 0..3  (q-chunk)  -- fastest: L2 reuse of x
    const int wch = blockIdx.y;          // 0..1  (w-chunk of 32)
    const int zz  = blockIdx.z;          // (b*G+g)*H + h
    const int h   = zz & (H_ - 1);
    const int bg  = zz >> 6;
    const int g   = bg & (G_ - 1);
    const int b   = bg >> 2;

    const int tid = threadIdx.x;

    // ---- y interpolation coefficients for this fine row h ----
    // src_y = (h + 0.5)/4 - 0.5 = h*0.25 - 0.375 ; edge clamp
    float fy  = h * 0.25f - 0.375f;
    float fyf = floorf(fy);
    float wy1 = fy - fyf;                 // weight on upper row
    int   h0  = (int)fyf;
    int   h1  = min(h0 + 1, HC_ - 1);
    h0 = max(h0, 0);

    // ---- phase 1a: Cy[q][k][wc] = lerp_y(coarse) ----
    // coarse attn layout: ((((g*B+b)*T + q)*T + k)*HC + hc)*WC + wc
    const float* cb = attn + ((((size_t)g * B_ + b) * T_ + (size_t)qc * TQ) * T_) * (HC_ * WC_);
    #pragma unroll
    for (int i = 0; i < (TQ * T_ * WC_) / 256; ++i) {    // 16 iters
        int idx = i * 256 + tid;
        int wc  = idx & (WC_ - 1);
        int qk  = idx >> 4;               // q*32 + k
        const float* p = cb + (size_t)qk * (HC_ * WC_) + wc;
        float v0 = p[h0 * WC_];
        float v1 = p[h1 * WC_];
        Cy[idx] = v0 + wy1 * (v1 - v0);
    }
    __syncthreads();

    // ---- phase 1b: Ash[q][k][w] = lerp_x(Cy) ----
    {
        const int wl = tid & 31;                  // constant across iters
        const int wf = wch * 32 + wl;
        float fx  = wf * 0.25f - 0.375f;
        float fxf = floorf(fx);
        float wx1 = fx - fxf;
        int   w0  = (int)fxf;
        int   w1  = min(w0 + 1, WC_ - 1);
        w0 = max(w0, 0);
        const int kq0 = tid >> 5;                 // 0..7
        #pragma unroll
        for (int i = 0; i < (TQ * T_ * 32) / 256; ++i) {  // 32 iters
            int kq = i * 8 + kq0;                 // q*32 + k
            float v0 = Cy[kq * WC_ + w0];
            float v1 = Cy[kq * WC_ + w1];
            Ash[kq * 32 + wl] = v0 + wx1 * (v1 - v0);
        }
    }
    __syncthreads();

    // ---- phase 2: per-pixel GEMM slice ----
    // thread: w lane (32), channel group cg (8) -> 4 channels each
    const int wl = tid & 31;
    const int cg = tid >> 5;
    const int wf = wch * 32 + wl;
    const int cbase = g * CPG + cg * 4;

    const float* xp = x + ((size_t)b * T_ * C_ + cbase) * HW_ + (size_t)h * W_ + wf;

    float acc[TQ][4];
    #pragma unroll
    for (int q = 0; q < TQ; ++q) {
        acc[q][0] = 0.f; acc[q][1] = 0.f; acc[q][2] = 0.f; acc[q][3] = 0.f;
    }

    #pragma unroll 4
    for (int k = 0; k < T_; ++k) {
        const float* xk = xp + (size_t)k * CHW_;
        float x0 = xk[0];
        float x1 = xk[HW_];
        float x2 = xk[2 * HW_];
        float x3 = xk[3 * HW_];
        #pragma unroll
        for (int q = 0; q < TQ; ++q) {
            float a = Ash[(q * T_ + k) * 32 + wl];
            acc[q][0] += a * x0;
            acc[q][1] += a * x1;
            acc[q][2] += a * x2;
            acc[q][3] += a * x3;
        }
    }

    // ---- store: out[(((b*T+q)*C + c)*H + h)*W + w] ----
    float* ob = out + (((size_t)b * T_ + (size_t)qc * TQ) * C_ + cbase) * HW_ + (size_t)h * W_ + wf;
    #pragma unroll
    for (int q = 0; q < TQ; ++q) {
        #pragma unroll
        for (int cc = 0; cc < 4; ++cc) {
            ob[(size_t)q * CHW_ + (size_t)cc * HW_] = acc[q][cc];
        }
    }
}

extern "C" void kernel_launch(void* const* d_in, const int* in_sizes, int n_in,
                              void* d_out, int out_size)
{
    const float* x    = (const float*)d_in[0];   // (2,32,128,64,64)
    const float* attn = (const float*)d_in[1];   // (4,2,32,32,16,16)
    float* out        = (float*)d_out;           // (2,32,128,64,64)

    dim3 grid(T_ / TQ /*4 q-chunks*/, W_ / 32 /*2 w-chunks*/, B_ * G_ * H_ /*512*/);
    temporal_agg_kernel<<<grid, 256>>>(x, attn, out);
}